// round 17
// baseline (speedup 1.0000x reference)
#include <cuda_runtime.h>
#include <cuda_bf16.h>
#include <float.h>
#include <math.h>

#define NUM_CLASSES 13
#define C1 (NUM_CLASSES + 1)   // 14
#define Bn 64
#define Qn 900
#define Tn 128
#define NTH 256                // uniform block size (8 warps)
#define NWARP (NTH / 32)
#define JPT 4                  // columns per thread (float4)
#define NACT (Qn / JPT)        // 225 active scan threads
#define TSPLIT 2
#define TCH (Tn / TSPLIT)      // 64 targets per cost CTA
#define COST_XB 4              // 4 x-blocks of 256 columns
#define COST_PER_IMG (COST_XB * TSPLIT)   // 8
#define RM_PER_IMG (Tn / NWARP)           // 16 (8 rows per CTA, 1 per warp)
#define GRP (COST_PER_IMG + RM_PER_IMG)   // 24
#define TOTAL_CTAS (Bn + Bn * GRP)        // 64 + 1536 = 1600

// ---- scratch (static device globals; no allocation allowed) ----
__device__ __align__(256) float g_cost[Bn * Tn * Qn];   // cost[b][t][q]
__device__ float  g_lse[Bn * Qn];         // logsumexp per (b,q)
__device__ float  g_rowu[Bn * Tn];        // row minima (exact matrix entries)
__device__ int    g_rowarg[Bn * Tn];      // argmin col (1-based)
__device__ double g_partial[Bn];          // per-image loss
__device__ int    g_ctr = 0;              // loss completion counter
__device__ int    g_done_cost[Bn];        // per-image cost-CTA counter (reset by consumer)
__device__ int    g_done_rm[Bn];          // per-image rowmin-CTA counter (reset by consumer)

// order-preserving float <-> uint32 (no NaNs in costs)
__device__ __forceinline__ unsigned enc_f(float f) {
    unsigned u = __float_as_uint(f);
    return (u & 0x80000000u) ? ~u : (u | 0x80000000u);
}
__device__ __forceinline__ float dec_f(unsigned e) {
    unsigned x = (e & 0x80000000u) ? (e & 0x7fffffffu) : ~e;
    return __uint_as_float(x);
}

// ---- shared memory overlays (one static block, per-role casts) ----
struct CostSmem {
    float4 tb4[TCH];
    int    lab[TCH];
    float  negp[C1][NTH];
};
struct HungSmem {
    float u[Tn + 1];
    int   way[Qn + 1];
    int   p[Qn + 1];
    int   rowq[Tn + 1];
    unsigned char assigned[Tn + 1];
    unsigned long long gmin[2];
    double sred[4][NWARP];
    int   last;
};
#define SMEM_BYTES (sizeof(CostSmem) > sizeof(HungSmem) ? sizeof(CostSmem) : sizeof(HungSmem))

// ============================================================================
// role: cost — image img, xblk in [0,4), seg in {0,1}
// ============================================================================
__device__ void cost_role(int img, int xblk, int tseg,
                          const float* __restrict__ pc, const float* __restrict__ pb,
                          const int* __restrict__ lab, const float* __restrict__ tb,
                          char* smem_raw)
{
    CostSmem* sm = (CostSmem*)smem_raw;
    int b   = img;
    int t0  = tseg * TCH;
    int tid = threadIdx.x;
    int q   = xblk * NTH + tid;

    for (int i = tid; i < TCH; i += NTH) {
        sm->tb4[i] = reinterpret_cast<const float4*>(tb)[b * Tn + t0 + i];
        sm->lab[i] = lab[b * Tn + t0 + i];
    }

    float4 pbq = make_float4(0.f, 0.f, 0.f, 0.f);
    if (q < Qn) {
        const float* lg = pc + (size_t)(b * Qn + q) * C1;
        float m = lg[0];
        #pragma unroll
        for (int c = 1; c < C1; c++) m = fmaxf(m, lg[c]);
        float e[C1]; float se = 0.f;
        #pragma unroll
        for (int c = 0; c < C1; c++) { e[c] = __expf(lg[c] - m); se += e[c]; }
        float inv = 1.0f / se;
        #pragma unroll
        for (int c = 0; c < C1; c++) sm->negp[c][tid] = -e[c] * inv;
        if (tseg == 0) g_lse[b * Qn + q] = m + logf(se);
        pbq = *reinterpret_cast<const float4*>(pb + (size_t)(b * Qn + q) * 4);
    }
    __syncthreads();

    if (q < Qn) {
        float* crow = g_cost + (size_t)b * Tn * Qn + (size_t)t0 * Qn + q;
        #pragma unroll 8
        for (int t = 0; t < TCH; t++) {
            float4 tb4 = sm->tb4[t];
            float cc = sm->negp[sm->lab[t]][tid];
            float cb = fabsf(pbq.x - tb4.x) + fabsf(pbq.y - tb4.y)
                     + fabsf(pbq.z - tb4.z) + fabsf(pbq.w - tb4.w);
            crow[(size_t)t * Qn] = cb + cc;
        }
    }

    __threadfence();
    __syncthreads();
    if (tid == 0) atomicAdd(&g_done_cost[img], 1);
}

// ============================================================================
// role: rowmin — image img, 8 rows (one per warp), rows rmidx*8 .. +7
// ============================================================================
__device__ void rowmin_role(int img, int rmidx)
{
    int tid = threadIdx.x;
    int lane = tid & 31, warp = tid >> 5;

    if (tid == 0) {
        while (*(volatile int*)&g_done_cost[img] < COST_PER_IMG) __nanosleep(64);
    }
    __syncthreads();
    __threadfence();

    int row  = rmidx * NWARP + warp;
    int widx = img * Tn + row;
    const float* crow = g_cost + (size_t)widx * Qn;

    unsigned long long best = ~0ull;
    #pragma unroll
    for (int s = 0; s < 8; s++) {
        if (s == 7 && lane != 0) break;
        int j0 = (s < 7) ? (s * 128 + lane * 4) : 896;
        float4 c4 = __ldg(reinterpret_cast<const float4*>(crow + j0));
        #pragma unroll
        for (int k = 0; k < 4; k++) {
            unsigned long long e =
                ((unsigned long long)enc_f((&c4.x)[k]) << 32) | (unsigned)(j0 + k + 1);
            if (e < best) best = e;
        }
    }
    #pragma unroll
    for (int s = 16; s; s >>= 1) {
        unsigned long long o = __shfl_down_sync(0xffffffffu, best, s);
        if (o < best) best = o;
    }
    if (lane == 0) {
        g_rowu[widx]   = dec_f((unsigned)(best >> 32));
        g_rowarg[widx] = (int)(best & 0xffffffffu);
    }

    __threadfence();
    __syncthreads();
    if (tid == 0) atomicAdd(&g_done_rm[img], 1);
}

// ============================================================================
// role: hungarian + fused loss (R16-proven body), spin-gated on readiness
// ============================================================================
__device__ void hungarian_role(int b,
                               const float* __restrict__ pc, const float* __restrict__ pb,
                               const int* __restrict__ lab, const float* __restrict__ tb,
                               float* __restrict__ out, char* smem_raw)
{
    HungSmem* sm = (HungSmem*)smem_raw;
    int tid = threadIdx.x;
    int lane = tid & 31, warp = tid >> 5;

    if (tid == 0) {
        while (*(volatile int*)&g_done_rm[b] < RM_PER_IMG) __nanosleep(64);
        g_done_cost[b] = 0;     // safe: all readers finished; ready for next replay
        g_done_rm[b]   = 0;
    }
    __syncthreads();
    __threadfence();

    for (int j = tid; j <= Qn; j += NTH) sm->p[j] = 0;
    for (int i = tid; i < Tn; i += NTH) {
        sm->u[i + 1]    = g_rowu[b * Tn + i];
        sm->rowq[i + 1] = g_rowarg[b * Tn + i];
    }
    if (tid == 0) { sm->gmin[0] = ~0ull; sm->gmin[1] = ~0ull; }
    __syncthreads();

    const float* cost = g_cost + (size_t)b * Tn * Qn;
    const bool valid = (tid < NACT);
    const int  jbase = JPT * tid + 1;     // first owned column (1-based)

    float v4[JPT], minv4[JPT], tu4[JPT];
    unsigned mask = 0;
    #pragma unroll
    for (int k = 0; k < JPT; k++) { v4[k] = 0.f; minv4[k] = FLT_MAX; }

    // greedy assignment (serial, trivial)
    if (tid == 0) {
        for (int i = 1; i <= Tn; i++) {
            int j = sm->rowq[i];
            if (sm->p[j] == 0) { sm->p[j] = i; sm->assigned[i] = 1; }
            else sm->assigned[i] = 0;
        }
    }
    __syncthreads();

    // Dijkstra phases (deferred duals, register column state)
    for (int i = 1; i <= Tn; i++) {
        if (sm->assigned[i]) continue;
        if (tid == 0) sm->p[0] = i;

        int   i0 = i;
        float C  = 0.f;
        int   lastj1 = 0;
        int   it = 0;
        int   jfinal; float Cf;

        while (true) {
            int par = it & 1;
            float4 cr = make_float4(0.f, 0.f, 0.f, 0.f);
            if (valid) cr = __ldg(reinterpret_cast<const float4*>(
                                  cost + (size_t)(i0 - 1) * Qn + (jbase - 1)));
            float aC = sm->u[i0] - C;

            unsigned benc = 0xFFFFFFFFu; int bj = 0x7FFFFFFF;
            if (valid) {
                #pragma unroll
                for (int k = 0; k < JPT; k++) {
                    if (!(mask & (1u << k))) {
                        float r = (&cr.x)[k] - aC - v4[k];
                        if (r < minv4[k]) { minv4[k] = r; sm->way[jbase + k] = lastj1; }
                        unsigned e = enc_f(minv4[k]);
                        if (e < benc) { benc = e; bj = jbase + k; }
                    }
                }
            }
            unsigned m = __reduce_min_sync(0xffffffffu, benc);
            int cand = (benc == m) ? bj : 0x7FFFFFFF;
            int jm = __reduce_min_sync(0xffffffffu, cand);
            if (lane == 0)
                atomicMin(&sm->gmin[par],
                          ((unsigned long long)m << 32) | (unsigned)jm);
            if (tid == 0) sm->gmin[par ^ 1] = ~0ull;
            __syncthreads();

            unsigned long long g = sm->gmin[par];
            unsigned ge = (unsigned)(g >> 32);
            int j1 = (int)(g & 0xFFFFFFFFu);
            float Cn = dec_f(ge);
            int i0n = sm->p[j1];
            if (i0n == 0) { jfinal = j1; Cf = Cn; break; }
            unsigned k1 = (unsigned)(j1 - jbase);
            if (valid && k1 < JPT) { mask |= 1u << k1; tu4[k1] = Cn; }
            lastj1 = j1; C = Cn; i0 = i0n; it++;
        }

        #pragma unroll
        for (int k = 0; k < JPT; k++) {
            if (mask & (1u << k)) {
                float dv = Cf - tu4[k];
                v4[k] -= dv;
                sm->u[sm->p[jbase + k]] += dv;
            }
            minv4[k] = FLT_MAX;
        }
        mask = 0;
        if (tid == 0) { sm->u[i] += Cf; sm->gmin[0] = ~0ull; }
        __syncthreads();
        if (tid == 0) {
            int j0 = jfinal;
            while (j0) { int jp = sm->way[j0]; sm->p[j0] = sm->p[jp]; j0 = jp; }
            sm->assigned[i] = 1;
        }
        __syncthreads();
    }

    // qi per target
    for (int j = tid + 1; j <= Qn; j += NTH) {
        int pi = sm->p[j];
        if (pi > 0) sm->rowq[pi] = j - 1;
    }
    __syncthreads();

    // ================= fused per-image loss =================
    int* tcl = sm->way;
    double l1 = 0.0, gsum = 0.0;
    if (tid < Tn) {
        int t = tid;
        int qi = sm->rowq[t + 1];
        const float4 P = *reinterpret_cast<const float4*>(pb + (size_t)(b * Qn + qi) * 4);
        const float4 G = *reinterpret_cast<const float4*>(tb + (size_t)(b * Tn + t) * 4);
        double px = P.x, py = P.y, pw = P.z, ph = P.w;
        double gx = G.x, gy = G.y, gw = G.z, gh = G.w;
        l1 = fabs(px - gx) + fabs(py - gy) + fabs(pw - gw) + fabs(ph - gh);

        double p0 = px - 0.5 * pw, p1 = py - 0.5 * ph, p2 = px + 0.5 * pw, p3 = py + 0.5 * ph;
        double g0 = gx - 0.5 * gw, g1 = gy - 0.5 * gh, g2 = gx + 0.5 * gw, g3 = gy + 0.5 * gh;
        double a1 = (p2 - p0) * (p3 - p1);
        double a2 = (g2 - g0) * (g3 - g1);
        double iw = fmin(p2, g2) - fmax(p0, g0); iw = iw > 0.0 ? iw : 0.0;
        double ih = fmin(p3, g3) - fmax(p1, g1); ih = ih > 0.0 ? ih : 0.0;
        double inter = iw * ih;
        double uni = a1 + a2 - inter;
        double iou = inter / uni;
        double cw = fmax(p2, g2) - fmin(p0, g0);
        double ch = fmax(p3, g3) - fmin(p1, g1);
        double ac = cw * ch;
        double giou = iou - (ac - uni) / ac;
        gsum = 1.0 - giou;
    }

    for (int q = tid; q < Qn; q += NTH) tcl[q] = NUM_CLASSES;
    __syncthreads();
    if (tid < Tn) tcl[sm->rowq[tid + 1]] = lab[b * Tn + tid];
    __syncthreads();

    double wn = 0.0, ws = 0.0;
    for (int q = tid; q < Qn; q += NTH) {
        int c = tcl[q];
        double w = (c == NUM_CLASSES) ? 0.05 : 1.0;
        double nll = (double)g_lse[b * Qn + q] - (double)pc[(size_t)(b * Qn + q) * C1 + c];
        wn += w * nll; ws += w;
    }

    #pragma unroll
    for (int s = 16; s; s >>= 1) {
        l1   += __shfl_down_sync(0xffffffffu, l1, s);
        gsum += __shfl_down_sync(0xffffffffu, gsum, s);
        wn   += __shfl_down_sync(0xffffffffu, wn, s);
        ws   += __shfl_down_sync(0xffffffffu, ws, s);
    }
    if (lane == 0) {
        sm->sred[0][warp] = l1; sm->sred[1][warp] = gsum;
        sm->sred[2][warp] = wn; sm->sred[3][warp] = ws;
    }
    __syncthreads();

    if (tid == 0) {
        double l1t = 0.0, gst = 0.0, wnt = 0.0, wst = 0.0;
        #pragma unroll
        for (int w = 0; w < NWARP; w++) {
            l1t += sm->sred[0][w]; gst += sm->sred[1][w];
            wnt += sm->sred[2][w]; wst += sm->sred[3][w];
        }
        double bbox = 5.0 * (l1t / (Tn * 4.0)) + 2.0 * (gst / Tn);
        g_partial[b] = bbox + wnt / wst;
        __threadfence();
        int t = atomicAdd(&g_ctr, 1);
        sm->last = (t == Bn - 1);
    }
    __syncthreads();

    if (sm->last && warp == 0) {
        double val = ((volatile double*)g_partial)[lane]
                   + ((volatile double*)g_partial)[lane + 32];
        #pragma unroll
        for (int s = 16; s; s >>= 1)
            val += __shfl_down_sync(0xffffffffu, val, s);
        if (lane == 0) {
            out[0] = (float)(val / (double)(Bn * Tn));
            g_ctr = 0;
        }
    }
}

// ============================================================================
// fused dispatcher
// ============================================================================
__global__ __launch_bounds__(NTH) void fused_kernel(
    const float* __restrict__ pc, const float* __restrict__ pb,
    const int* __restrict__ lab, const float* __restrict__ tb,
    float* __restrict__ out)
{
    __shared__ __align__(16) char smem_raw[SMEM_BYTES];
    int bid = blockIdx.x;
    if (bid < Bn) {
        hungarian_role(bid, pc, pb, lab, tb, out, smem_raw);
    } else {
        int g = bid - Bn;
        int img = g / GRP;
        int r = g % GRP;
        if (r < COST_PER_IMG) cost_role(img, r % COST_XB, r / COST_XB, pc, pb, lab, tb, smem_raw);
        else                  rowmin_role(img, r - COST_PER_IMG);
    }
}

extern "C" void kernel_launch(void* const* d_in, const int* in_sizes, int n_in,
                              void* d_out, int out_size)
{
    const float* pc  = (const float*)d_in[0];   // predicted_class [64,900,14]
    const float* pb  = (const float*)d_in[1];   // predicted_bbox  [64,900,4]
    const int*   lab = (const int*)  d_in[2];   // target_labels   [64,128]
    const float* tb  = (const float*)d_in[3];   // target_boxes    [64,128,4]
    float* out = (float*)d_out;

    fused_kernel<<<TOTAL_CTAS, NTH>>>(pc, pb, lab, tb, out);
}